// round 8
// baseline (speedup 1.0000x reference)
#include <cuda_runtime.h>
#include <cuda_bf16.h>
#include <cstdint>

#define N0c   100000
#define N1c   25000
#define N2c   5000
#define E0c   800000
#define E1c   160000
#define DIN   256
#define DHID  256
#define DOUT  128
#define EPSc  1e-5f
#define NEG_SLOPE 0.01f
#define MAXD  48

// ---------------- scratch (device globals; no allocation allowed) ----------------
__device__ float g_agg1[(size_t)N1c * DIN];   // mean-aggregated, tf32-rounded
__device__ float g_h[(size_t)N1c * DHID];     // hidden, tf32-rounded
__device__ float g_agg2[(size_t)N2c * DHID];  // tf32-rounded
__device__ float g_xr[(size_t)N1c * DIN];     // x[:N1] tf32-rounded (root of GEMM1)
__device__ float g_w1l[DIN * DHID], g_w1r[DIN * DHID];
__device__ float g_w2l[DHID * DOUT], g_w2r[DHID * DOUT];
__device__ int   g_icnt1[N1c];
__device__ int   g_icnt2[N2c];
__device__ int   g_slot1[(size_t)N1c * MAXD];
__device__ int   g_slot2[(size_t)N2c * MAXD];

__device__ __forceinline__ float tf32r(float f) {
    uint32_t u;
    asm("cvt.rna.tf32.f32 %0, %1;" : "=r"(u) : "f"(f));
    return __uint_as_float(u);
}

// ---------------- zero counters ----------------
__global__ void zero_counts() {
    int i = blockIdx.x * blockDim.x + threadIdx.x;
    int stride = gridDim.x * blockDim.x;
    for (int k = i; k < N1c; k += stride) g_icnt1[k] = 0;
    for (int k = i; k < N2c; k += stride) g_icnt2[k] = 0;
}

// ---------------- pre-round weights + x-root to tf32 precision ----------------
__global__ void round_operands(const float* __restrict__ x,
                               const float* __restrict__ W1l, const float* __restrict__ W1r,
                               const float* __restrict__ W2l, const float* __restrict__ W2r) {
    int i = blockIdx.x * blockDim.x + threadIdx.x;
    int stride = gridDim.x * blockDim.x;
    for (int k = i; k < DIN * DHID; k += stride) {
        g_w1l[k] = tf32r(W1l[k]);
        g_w1r[k] = tf32r(W1r[k]);
    }
    for (int k = i; k < DHID * DOUT; k += stride) {
        g_w2l[k] = tf32r(W2l[k]);
        g_w2r[k] = tf32r(W2r[k]);
    }
    // x root rows, vectorized
    const float4* xs = (const float4*)x;
    float4* xr = (float4*)g_xr;
    for (int k = i; k < N1c * DIN / 4; k += stride) {
        float4 v = __ldg(&xs[k]);
        v.x = tf32r(v.x); v.y = tf32r(v.y); v.z = tf32r(v.z); v.w = tf32r(v.w);
        xr[k] = v;
    }
}

// ---------------- phase A: mask + bucket edges by dst ----------------
template <int LAYER>
__global__ void compact_edges(const int* __restrict__ src,
                              const int* __restrict__ dst,
                              const int* __restrict__ val,
                              const int* __restrict__ ts,
                              const int* __restrict__ time_p,
                              const int* __restrict__ interval_p,
                              float* __restrict__ mask_out) {
    int e = blockIdx.x * blockDim.x + threadIdx.x;
    int t0 = __ldg(time_p);
    int iv = __ldg(interval_p);
    int t = __ldg(&ts[__ldg(&val[e])]);
    bool m = (t >= t0) && (t < t0 + iv);

    if (LAYER == 1 && mask_out != nullptr) mask_out[e] = m ? 1.0f : 0.0f;
    if (!m) return;

    int d = __ldg(&dst[e]);
    int* cnt = (LAYER == 0) ? g_icnt1 : g_icnt2;
    int* slot = (LAYER == 0) ? g_slot1 : g_slot2;
    int p = atomicAdd(&cnt[d], 1);
    if (p < MAXD) slot[(size_t)d * MAXD + p] = __ldg(&src[e]);
}

// ---------------- phase B: warp per dst node, gather + mean (tf32-rounded out) ----------------
template <int LAYER>
__global__ void gather_mean(const float* __restrict__ feat) {
    constexpr int NR = (LAYER == 0) ? N1c : N2c;
    const int* cnt = (LAYER == 0) ? g_icnt1 : g_icnt2;
    const int* slot = (LAYER == 0) ? g_slot1 : g_slot2;
    const float* fsrc = (LAYER == 0) ? feat : (const float*)g_h;
    float* agg = (LAYER == 0) ? g_agg1 : g_agg2;

    int w = (blockIdx.x * blockDim.x + threadIdx.x) >> 5;
    if (w >= NR) return;
    int lane = threadIdx.x & 31;

    int deg = __ldg(&cnt[w]);
    int dc = (deg < MAXD) ? deg : MAXD;
    const int* sl = slot + (size_t)w * MAXD;

    float4 s0 = make_float4(0.f, 0.f, 0.f, 0.f);
    float4 s1 = make_float4(0.f, 0.f, 0.f, 0.f);
    for (int e = 0; e < dc; e++) {
        int s = __ldg(&sl[e]);
        const float4* xs = (const float4*)(fsrc + (size_t)s * DHID);
        float4 a = __ldg(&xs[lane]);
        float4 b = __ldg(&xs[lane + 32]);
        s0.x += a.x; s0.y += a.y; s0.z += a.z; s0.w += a.w;
        s1.x += b.x; s1.y += b.y; s1.z += b.z; s1.w += b.w;
    }
    float r = 1.0f / (float)((deg > 0) ? deg : 1);
    s0.x = tf32r(s0.x * r); s0.y = tf32r(s0.y * r);
    s0.z = tf32r(s0.z * r); s0.w = tf32r(s0.w * r);
    s1.x = tf32r(s1.x * r); s1.y = tf32r(s1.y * r);
    s1.z = tf32r(s1.z * r); s1.w = tf32r(s1.w * r);
    float4* ag = (float4*)(agg + (size_t)w * DHID);
    ag[lane] = s0;
    ag[lane + 32] = s1;
}

// ---------------- TF32 tensor-core GEMM, cp.async 3-stage, pre-rounded operands ----------------
__device__ __forceinline__ void mma_tf32(float* c, const uint32_t* a, const uint32_t* b) {
    asm volatile(
        "mma.sync.aligned.m16n8k8.row.col.f32.tf32.tf32.f32 "
        "{%0,%1,%2,%3}, {%4,%5,%6,%7}, {%8,%9}, {%0,%1,%2,%3};"
        : "+f"(c[0]), "+f"(c[1]), "+f"(c[2]), "+f"(c[3])
        : "r"(a[0]), "r"(a[1]), "r"(a[2]), "r"(a[3]), "r"(b[0]), "r"(b[1]));
}

__device__ __forceinline__ void cp_async16(uint32_t dst, const void* src, int srcsize) {
    asm volatile("cp.async.cg.shared.global [%0], [%1], 16, %2;"
                 :: "r"(dst), "l"(src), "r"(srcsize));
}

// Block tile: BM = IM*32, BN = JN*32, BK = 32; 8 warps (2m x 4n); 3-stage pipeline.
template <int LAYER, int IM, int JN>
__global__ __launch_bounds__(256, 2) void gemm_tf32(
    const float* __restrict__ bias,
    const float* __restrict__ gam, const float* __restrict__ bet,
    const float* __restrict__ rm, const float* __restrict__ rv,
    float* __restrict__ outp) {
    constexpr int M = (LAYER == 1) ? N1c : N2c;
    constexpr int N = (LAYER == 1) ? DHID : DOUT;
    constexpr bool DO_BN = (LAYER == 1);
    constexpr int BM = IM * 32;
    constexpr int BN = JN * 32;
    constexpr int AS_STRIDE = 36;
    constexpr int BS_STRIDE = BN + 4;
    constexpr int ASZ = BM * AS_STRIDE;
    constexpr int BSZ = 32 * BS_STRIDE;
    constexpr int BUFSZ = ASZ + BSZ;
    constexpr int B4 = BN / 4;

    const float* Aagg  = (LAYER == 1) ? g_agg1 : g_agg2;
    const float* Aroot = (LAYER == 1) ? g_xr : (const float*)g_h;
    const float* B1    = (LAYER == 1) ? g_w1l : g_w2l;
    const float* B2    = (LAYER == 1) ? g_w1r : g_w2r;
    float* Out = (LAYER == 1) ? g_h : outp;

    extern __shared__ __align__(16) uint32_t sm[];

    const int tid = threadIdx.x;
    const int lane = tid & 31;
    const int wid = tid >> 5;
    const int wm = wid >> 2;
    const int wn = wid & 3;
    const int bm = blockIdx.y * BM;
    const int bn = blockIdx.x * BN;

    const uint32_t smbase = (uint32_t)__cvta_generic_to_shared(sm);

    auto load_tile = [&](int t) {
        const bool ia = (t < 8);
        const float* Aptr = ia ? Aagg : Aroot;
        const float* Bptr = ia ? B1 : B2;
        const int kk = (t * 32) & 255;
        const uint32_t abase = smbase + (uint32_t)((t % 3) * BUFSZ) * 4u;
        const uint32_t bbase = abase + (uint32_t)ASZ * 4u;
#pragma unroll
        for (int i = 0; i < IM; i++) {
            int idx = tid + i * 256;
            int m = idx >> 3, kg = idx & 7;
            int row = bm + m;
            int ok = (row < M) ? 16 : 0;
            int rc = (row < M) ? row : (M - 1);
            cp_async16(abase + (uint32_t)(m * AS_STRIDE + 4 * kg) * 4u,
                       Aptr + (size_t)rc * 256 + kk + 4 * kg, ok);
        }
#pragma unroll
        for (int i = 0; i < JN; i++) {
            int idx = tid + i * 256;
            int k = idx / B4, ng = idx % B4;
            cp_async16(bbase + (uint32_t)(k * BS_STRIDE + 4 * ng) * 4u,
                       Bptr + (size_t)(kk + k) * N + bn + 4 * ng, 16);
        }
        asm volatile("cp.async.commit_group;");
    };

    float acc[IM][JN][4];
#pragma unroll
    for (int i = 0; i < IM; i++)
#pragma unroll
        for (int j = 0; j < JN; j++)
#pragma unroll
            for (int r = 0; r < 4; r++) acc[i][j][r] = 0.0f;

    load_tile(0);
    load_tile(1);

    for (int t = 0; t < 16; t++) {
        if (t < 15) {
            asm volatile("cp.async.wait_group 1;");
        } else {
            asm volatile("cp.async.wait_group 0;");
        }
        __syncthreads();
        if (t + 2 < 16) load_tile(t + 2);

        const uint32_t* As = sm + (t % 3) * BUFSZ;
        const uint32_t* Bs = As + ASZ;

#pragma unroll
        for (int ks = 0; ks < 4; ks++) {
            uint32_t af[IM][4], bf[JN][2];
            const int col = ks * 8 + (lane & 3);
            const int rbase = wm * (IM * 16) + (lane >> 2);
#pragma unroll
            for (int i = 0; i < IM; i++) {
                int r = rbase + i * 16;
                af[i][0] = As[r * AS_STRIDE + col];
                af[i][1] = As[(r + 8) * AS_STRIDE + col];
                af[i][2] = As[r * AS_STRIDE + col + 4];
                af[i][3] = As[(r + 8) * AS_STRIDE + col + 4];
            }
#pragma unroll
            for (int j = 0; j < JN; j++) {
                int n = wn * (JN * 8) + j * 8 + (lane >> 2);
                bf[j][0] = Bs[col * BS_STRIDE + n];
                bf[j][1] = Bs[(col + 4) * BS_STRIDE + n];
            }
#pragma unroll
            for (int i = 0; i < IM; i++)
#pragma unroll
                for (int j = 0; j < JN; j++) mma_tf32(acc[i][j], af[i], bf[j]);
        }
    }

    float cb[JN][2], cs[JN][2], csh[JN][2];
#pragma unroll
    for (int j = 0; j < JN; j++) {
#pragma unroll
        for (int q = 0; q < 2; q++) {
            int c = bn + wn * (JN * 8) + j * 8 + 2 * (lane & 3) + q;
            cb[j][q] = bias[c];
            if (DO_BN) {
                float s = gam[c] * rsqrtf(rv[c] + EPSc);
                cs[j][q] = s;
                csh[j][q] = bet[c] - rm[c] * s;
            }
        }
    }

#pragma unroll
    for (int i = 0; i < IM; i++) {
        int r0 = bm + wm * (IM * 16) + i * 16 + (lane >> 2);
#pragma unroll
        for (int j = 0; j < JN; j++) {
            int c = bn + wn * (JN * 8) + j * 8 + 2 * (lane & 3);
#pragma unroll
            for (int half = 0; half < 2; half++) {
                int r = r0 + half * 8;
                if (r >= M) continue;
                float y0 = acc[i][j][2 * half + 0] + cb[j][0];
                float y1 = acc[i][j][2 * half + 1] + cb[j][1];
                if (DO_BN) {
                    y0 = y0 * cs[j][0] + csh[j][0];
                    y1 = y1 * cs[j][1] + csh[j][1];
                    y0 = (y0 >= 0.f) ? y0 : NEG_SLOPE * y0;
                    y1 = (y1 >= 0.f) ? y1 : NEG_SLOPE * y1;
                    // h is consumed only as a tf32 GEMM operand / mean input: round once here
                    y0 = tf32r(y0);
                    y1 = tf32r(y1);
                }
                float2 o = make_float2(y0, y1);
                *(float2*)(Out + (size_t)r * N + c) = o;
            }
        }
    }
}

#define SMEM1 ((128 * 36 + 32 * 132) * 3 * 4)
#define SMEM2 ((64 * 36 + 32 * 68) * 3 * 4)

// ---------------- launch ----------------
extern "C" void kernel_launch(void* const* d_in, const int* in_sizes, int n_in,
                              void* d_out, int out_size) {
    const float* x    = (const float*)d_in[0];
    const int* src0   = (const int*)d_in[1];
    const int* dst0   = (const int*)d_in[2];
    const int* val0   = (const int*)d_in[3];
    const int* src1   = (const int*)d_in[4];
    const int* dst1   = (const int*)d_in[5];
    const int* val1   = (const int*)d_in[6];
    const int* ts     = (const int*)d_in[7];
    const int* timep  = (const int*)d_in[8];
    const int* intvp  = (const int*)d_in[9];
    const float* W1l  = (const float*)d_in[10];
    const float* W1r  = (const float*)d_in[11];
    const float* b1   = (const float*)d_in[12];
    const float* g1   = (const float*)d_in[13];
    const float* bt1  = (const float*)d_in[14];
    const float* rm1  = (const float*)d_in[15];
    const float* rv1  = (const float*)d_in[16];
    const float* W2l  = (const float*)d_in[17];
    const float* W2r  = (const float*)d_in[18];
    const float* b2   = (const float*)d_in[19];

    float* out = (float*)d_out;
    float* mask_out = (out_size >= N2c * DOUT + E1c) ? (out + N2c * DOUT) : nullptr;

    static bool attr_done = false;
    if (!attr_done) {
        cudaFuncSetAttribute((const void*)gemm_tf32<1, 4, 4>,
                             cudaFuncAttributeMaxDynamicSharedMemorySize, SMEM1);
        cudaFuncSetAttribute((const void*)gemm_tf32<2, 2, 2>,
                             cudaFuncAttributeMaxDynamicSharedMemorySize, SMEM2);
        attr_done = true;
    }

    // 1) zero per-dst counters + pre-round GEMM operands
    zero_counts<<<128, 256>>>();
    round_operands<<<1024, 256>>>(x, W1l, W1r, W2l, W2r);

    // 2) layer-0 mask + bucket-by-dst
    compact_edges<0><<<E0c / 256, 256>>>(src0, dst0, val0, ts, timep, intvp, nullptr);

    // 3) layer-0 gather + mean (warp per dst)
    gather_mean<0><<<(N1c * 32 + 255) / 256, 256>>>(x);

    // 4) GEMM1 (tf32, 3-stage, no in-loop cvt) + bias + BN + leaky -> g_h
    {
        dim3 grid(DHID / 128, (N1c + 127) / 128);
        gemm_tf32<1, 4, 4><<<grid, 256, SMEM1>>>(b1, g1, bt1, rm1, rv1, nullptr);
    }

    // 5) layer-1 mask + bucket (+ mask1 output)
    compact_edges<1><<<E1c / 256, 256>>>(src1, dst1, val1, ts, timep, intvp, mask_out);

    // 6) layer-1 gather + mean
    gather_mean<1><<<(N2c * 32 + 255) / 256, 256>>>(nullptr);

    // 7) GEMM2 (tf32, 3-stage) + bias -> out
    {
        dim3 grid(DOUT / 64, (N2c + 63) / 64);
        gemm_tf32<2, 2, 2><<<grid, 256, SMEM2>>>(b2, nullptr, nullptr, nullptr, nullptr, out);
    }
}

// round 11
// speedup vs baseline: 1.0246x; 1.0246x over previous
#include <cuda_runtime.h>
#include <cuda_bf16.h>
#include <cstdint>

#define N0c   100000
#define N1c   25000
#define N2c   5000
#define E0c   800000
#define E1c   160000
#define DIN   256
#define DHID  256
#define DOUT  128
#define EPSc  1e-5f
#define NEG_SLOPE 0.01f
#define MAXD  48

// ---------------- scratch (device globals) ----------------
__device__ float g_agg1[(size_t)N1c * DIN];   // mean-aggregated, tf32-rounded
__device__ float g_h[(size_t)N1c * DHID];     // hidden, tf32-rounded
__device__ float g_agg2[(size_t)N2c * DHID];  // tf32-rounded
__device__ float g_w1l[DIN * DHID], g_w1r[DIN * DHID];
__device__ float g_w2l[DHID * DOUT], g_w2r[DHID * DOUT];
__device__ int   g_icnt1[N1c];
__device__ int   g_icnt2[N2c];
__device__ int   g_slot1[(size_t)N1c * MAXD];
__device__ int   g_slot2[(size_t)N2c * MAXD];

__device__ __forceinline__ float tf32r(float f) {
    uint32_t u;
    asm("cvt.rna.tf32.f32 %0, %1;" : "=r"(u) : "f"(f));
    return __uint_as_float(u);
}
__device__ __forceinline__ uint32_t f2tf(float f) {
    uint32_t u;
    asm("cvt.rna.tf32.f32 %0, %1;" : "=r"(u) : "f"(f));
    return u;
}

// ---------------- zero counters + pre-round weights (tiny: 2.6 MB) ----------------
__global__ void prep(const float* __restrict__ W1l, const float* __restrict__ W1r,
                     const float* __restrict__ W2l, const float* __restrict__ W2r) {
    int i = blockIdx.x * blockDim.x + threadIdx.x;
    int stride = gridDim.x * blockDim.x;
    for (int k = i; k < N1c; k += stride) g_icnt1[k] = 0;
    for (int k = i; k < N2c; k += stride) g_icnt2[k] = 0;
    for (int k = i; k < DIN * DHID; k += stride) {
        g_w1l[k] = tf32r(__ldg(&W1l[k]));
        g_w1r[k] = tf32r(__ldg(&W1r[k]));
    }
    for (int k = i; k < DHID * DOUT; k += stride) {
        g_w2l[k] = tf32r(__ldg(&W2l[k]));
        g_w2r[k] = tf32r(__ldg(&W2r[k]));
    }
}

// ---------------- phase A: mask + bucket edges by dst ----------------
template <int LAYER>
__global__ void compact_edges(const int* __restrict__ src,
                              const int* __restrict__ dst,
                              const int* __restrict__ val,
                              const int* __restrict__ ts,
                              const int* __restrict__ time_p,
                              const int* __restrict__ interval_p,
                              float* __restrict__ mask_out) {
    int e = blockIdx.x * blockDim.x + threadIdx.x;
    int t0 = __ldg(time_p);
    int iv = __ldg(interval_p);
    int t = __ldg(&ts[__ldg(&val[e])]);
    bool m = (t >= t0) && (t < t0 + iv);

    if (LAYER == 1 && mask_out != nullptr) mask_out[e] = m ? 1.0f : 0.0f;
    if (!m) return;

    int d = __ldg(&dst[e]);
    int* cnt = (LAYER == 0) ? g_icnt1 : g_icnt2;
    int* slot = (LAYER == 0) ? g_slot1 : g_slot2;
    int p = atomicAdd(&cnt[d], 1);
    if (p < MAXD) slot[(size_t)d * MAXD + p] = __ldg(&src[e]);
}

// ---------------- phase B: warp per dst node, gather + mean (2-edge unrolled) ----------------
template <int LAYER>
__global__ void gather_mean(const float* __restrict__ feat) {
    constexpr int NR = (LAYER == 0) ? N1c : N2c;
    const int* cnt = (LAYER == 0) ? g_icnt1 : g_icnt2;
    const int* slot = (LAYER == 0) ? g_slot1 : g_slot2;
    const float* fsrc = (LAYER == 0) ? feat : (const float*)g_h;
    float* agg = (LAYER == 0) ? g_agg1 : g_agg2;

    int w = (blockIdx.x * blockDim.x + threadIdx.x) >> 5;
    if (w >= NR) return;
    int lane = threadIdx.x & 31;

    int deg = __ldg(&cnt[w]);
    int dc = (deg < MAXD) ? deg : MAXD;
    const int* sl = slot + (size_t)w * MAXD;

    float4 s0 = make_float4(0.f, 0.f, 0.f, 0.f);
    float4 s1 = make_float4(0.f, 0.f, 0.f, 0.f);
    int e = 0;
    for (; e + 2 <= dc; e += 2) {
        int sa = __ldg(&sl[e]);
        int sb = __ldg(&sl[e + 1]);
        const float4* xa = (const float4*)(fsrc + (size_t)sa * DHID);
        const float4* xb = (const float4*)(fsrc + (size_t)sb * DHID);
        float4 a0 = __ldg(&xa[lane]);
        float4 a1 = __ldg(&xa[lane + 32]);
        float4 b0 = __ldg(&xb[lane]);
        float4 b1 = __ldg(&xb[lane + 32]);
        s0.x += a0.x + b0.x; s0.y += a0.y + b0.y;
        s0.z += a0.z + b0.z; s0.w += a0.w + b0.w;
        s1.x += a1.x + b1.x; s1.y += a1.y + b1.y;
        s1.z += a1.z + b1.z; s1.w += a1.w + b1.w;
    }
    if (e < dc) {
        int sa = __ldg(&sl[e]);
        const float4* xa = (const float4*)(fsrc + (size_t)sa * DHID);
        float4 a0 = __ldg(&xa[lane]);
        float4 a1 = __ldg(&xa[lane + 32]);
        s0.x += a0.x; s0.y += a0.y; s0.z += a0.z; s0.w += a0.w;
        s1.x += a1.x; s1.y += a1.y; s1.z += a1.z; s1.w += a1.w;
    }
    float r = 1.0f / (float)((deg > 0) ? deg : 1);
    s0.x = tf32r(s0.x * r); s0.y = tf32r(s0.y * r);
    s0.z = tf32r(s0.z * r); s0.w = tf32r(s0.w * r);
    s1.x = tf32r(s1.x * r); s1.y = tf32r(s1.y * r);
    s1.z = tf32r(s1.z * r); s1.w = tf32r(s1.w * r);
    float4* ag = (float4*)(agg + (size_t)w * DHID);
    ag[lane] = s0;
    ag[lane + 32] = s1;
}

// ---------------- TF32 tensor-core GEMM, cp.async 2-stage ----------------
__device__ __forceinline__ void mma_tf32(float* c, const uint32_t* a, const uint32_t* b) {
    asm volatile(
        "mma.sync.aligned.m16n8k8.row.col.f32.tf32.tf32.f32 "
        "{%0,%1,%2,%3}, {%4,%5,%6,%7}, {%8,%9}, {%0,%1,%2,%3};"
        : "+f"(c[0]), "+f"(c[1]), "+f"(c[2]), "+f"(c[3])
        : "r"(a[0]), "r"(a[1]), "r"(a[2]), "r"(a[3]), "r"(b[0]), "r"(b[1]));
}

__device__ __forceinline__ void cp_async16(uint32_t dst, const void* src, int srcsize) {
    asm volatile("cp.async.cg.shared.global [%0], [%1], 16, %2;"
                 :: "r"(dst), "l"(src), "r"(srcsize));
}

// Block tile: BM = IM*32, BN = JN*32, BK = 32; 8 warps (2m x 4n); 2-stage.
// A agg half + B always pre-rounded (raw loads). A root half needs cvt only for LAYER==1.
template <int LAYER, int IM, int JN>
__global__ __launch_bounds__(256, 2) void gemm_tf32(
    const float* __restrict__ xroot,   // LAYER==1 only
    const float* __restrict__ bias,
    const float* __restrict__ gam, const float* __restrict__ bet,
    const float* __restrict__ rm, const float* __restrict__ rv,
    float* __restrict__ outp) {
    constexpr int M = (LAYER == 1) ? N1c : N2c;
    constexpr int N = (LAYER == 1) ? DHID : DOUT;
    constexpr bool DO_BN = (LAYER == 1);
    constexpr int BM = IM * 32;
    constexpr int BN = JN * 32;
    constexpr int AS_STRIDE = 36;
    constexpr int BS_STRIDE = BN + 4;
    constexpr int ASZ = BM * AS_STRIDE;
    constexpr int BSZ = 32 * BS_STRIDE;
    constexpr int BUFSZ = ASZ + BSZ;
    constexpr int B4 = BN / 4;

    const float* Aagg  = (LAYER == 1) ? g_agg1 : g_agg2;
    const float* Aroot = (LAYER == 1) ? xroot : (const float*)g_h;
    const float* B1    = (LAYER == 1) ? g_w1l : g_w2l;
    const float* B2    = (LAYER == 1) ? g_w1r : g_w2r;
    float* Out = (LAYER == 1) ? g_h : outp;

    extern __shared__ __align__(16) uint32_t sm[];

    const int tid = threadIdx.x;
    const int lane = tid & 31;
    const int wid = tid >> 5;
    const int wm = wid >> 2;
    const int wn = wid & 3;
    const int bm = blockIdx.y * BM;
    const int bn = blockIdx.x * BN;

    const uint32_t smbase = (uint32_t)__cvta_generic_to_shared(sm);

    auto load_tile = [&](int t, int buf) {
        const bool ia = (t < 8);
        const float* Aptr = ia ? Aagg : Aroot;
        const float* Bptr = ia ? B1 : B2;
        const int kk = (t * 32) & 255;
        const uint32_t abase = smbase + (uint32_t)(buf * BUFSZ) * 4u;
        const uint32_t bbase = abase + (uint32_t)ASZ * 4u;
#pragma unroll
        for (int i = 0; i < IM; i++) {
            int idx = tid + i * 256;
            int m = idx >> 3, kg = idx & 7;
            int row = bm + m;
            int ok = (row < M) ? 16 : 0;
            int rc = (row < M) ? row : (M - 1);
            cp_async16(abase + (uint32_t)(m * AS_STRIDE + 4 * kg) * 4u,
                       Aptr + (size_t)rc * 256 + kk + 4 * kg, ok);
        }
#pragma unroll
        for (int i = 0; i < JN; i++) {
            int idx = tid + i * 256;
            int k = idx / B4, ng = idx % B4;
            cp_async16(bbase + (uint32_t)(k * BS_STRIDE + 4 * ng) * 4u,
                       Bptr + (size_t)(kk + k) * N + bn + 4 * ng, 16);
        }
        asm volatile("cp.async.commit_group;");
    };

    float acc[IM][JN][4];
#pragma unroll
    for (int i = 0; i < IM; i++)
#pragma unroll
        for (int j = 0; j < JN; j++)
#pragma unroll
            for (int r = 0; r < 4; r++) acc[i][j][r] = 0.0f;

    load_tile(0, 0);

    for (int t = 0; t < 16; t++) {
        if (t + 1 < 16) {
            load_tile(t + 1, (t + 1) & 1);
            asm volatile("cp.async.wait_group 1;");
        } else {
            asm volatile("cp.async.wait_group 0;");
        }
        __syncthreads();

        const uint32_t* As = sm + (t & 1) * BUFSZ;
        const uint32_t* Bs = As + ASZ;
        // root half of LAYER 1 reads raw x -> needs tf32 cvt on A frags
        const bool need_cvt = (LAYER == 1) && (t >= 8);

#pragma unroll
        for (int ks = 0; ks < 4; ks++) {
            uint32_t af[IM][4], bf[JN][2];
            const int col = ks * 8 + (lane & 3);
            const int rbase = wm * (IM * 16) + (lane >> 2);
#pragma unroll
            for (int i = 0; i < IM; i++) {
                int r = rbase + i * 16;
                af[i][0] = As[r * AS_STRIDE + col];
                af[i][1] = As[(r + 8) * AS_STRIDE + col];
                af[i][2] = As[r * AS_STRIDE + col + 4];
                af[i][3] = As[(r + 8) * AS_STRIDE + col + 4];
                if (need_cvt) {
#pragma unroll
                    for (int q = 0; q < 4; q++)
                        af[i][q] = f2tf(__uint_as_float(af[i][q]));
                }
            }
#pragma unroll
            for (int j = 0; j < JN; j++) {
                int n = wn * (JN * 8) + j * 8 + (lane >> 2);
                bf[j][0] = Bs[col * BS_STRIDE + n];
                bf[j][1] = Bs[(col + 4) * BS_STRIDE + n];
            }
#pragma unroll
            for (int i = 0; i < IM; i++)
#pragma unroll
                for (int j = 0; j < JN; j++) mma_tf32(acc[i][j], af[i], bf[j]);
        }
        __syncthreads();
    }

    float cb[JN][2], cs[JN][2], csh[JN][2];
#pragma unroll
    for (int j = 0; j < JN; j++) {
#pragma unroll
        for (int q = 0; q < 2; q++) {
            int c = bn + wn * (JN * 8) + j * 8 + 2 * (lane & 3) + q;
            cb[j][q] = bias[c];
            if (DO_BN) {
                float s = gam[c] * rsqrtf(rv[c] + EPSc);
                cs[j][q] = s;
                csh[j][q] = bet[c] - rm[c] * s;
            }
        }
    }

#pragma unroll
    for (int i = 0; i < IM; i++) {
        int r0 = bm + wm * (IM * 16) + i * 16 + (lane >> 2);
#pragma unroll
        for (int j = 0; j < JN; j++) {
            int c = bn + wn * (JN * 8) + j * 8 + 2 * (lane & 3);
#pragma unroll
            for (int half = 0; half < 2; half++) {
                int r = r0 + half * 8;
                if (r >= M) continue;
                float y0 = acc[i][j][2 * half + 0] + cb[j][0];
                float y1 = acc[i][j][2 * half + 1] + cb[j][1];
                if (DO_BN) {
                    y0 = y0 * cs[j][0] + csh[j][0];
                    y1 = y1 * cs[j][1] + csh[j][1];
                    y0 = (y0 >= 0.f) ? y0 : NEG_SLOPE * y0;
                    y1 = (y1 >= 0.f) ? y1 : NEG_SLOPE * y1;
                    // h consumed only as tf32 operand / mean input: round once here
                    y0 = tf32r(y0);
                    y1 = tf32r(y1);
                }
                float2 o = make_float2(y0, y1);
                *(float2*)(Out + (size_t)r * N + c) = o;
            }
        }
    }
}

#define SMEM1 ((128 * 36 + 32 * 132) * 2 * 4)
#define SMEM2 ((64 * 36 + 32 * 68) * 2 * 4)

// ---------------- launch ----------------
extern "C" void kernel_launch(void* const* d_in, const int* in_sizes, int n_in,
                              void* d_out, int out_size) {
    const float* x    = (const float*)d_in[0];
    const int* src0   = (const int*)d_in[1];
    const int* dst0   = (const int*)d_in[2];
    const int* val0   = (const int*)d_in[3];
    const int* src1   = (const int*)d_in[4];
    const int* dst1   = (const int*)d_in[5];
    const int* val1   = (const int*)d_in[6];
    const int* ts     = (const int*)d_in[7];
    const int* timep  = (const int*)d_in[8];
    const int* intvp  = (const int*)d_in[9];
    const float* W1l  = (const float*)d_in[10];
    const float* W1r  = (const float*)d_in[11];
    const float* b1   = (const float*)d_in[12];
    const float* g1   = (const float*)d_in[13];
    const float* bt1  = (const float*)d_in[14];
    const float* rm1  = (const float*)d_in[15];
    const float* rv1  = (const float*)d_in[16];
    const float* W2l  = (const float*)d_in[17];
    const float* W2r  = (const float*)d_in[18];
    const float* b2   = (const float*)d_in[19];

    float* out = (float*)d_out;
    float* mask_out = (out_size >= N2c * DOUT + E1c) ? (out + N2c * DOUT) : nullptr;

    static bool attr_done = false;
    if (!attr_done) {
        cudaFuncSetAttribute((const void*)gemm_tf32<1, 4, 4>,
                             cudaFuncAttributeMaxDynamicSharedMemorySize, SMEM1);
        cudaFuncSetAttribute((const void*)gemm_tf32<2, 2, 2>,
                             cudaFuncAttributeMaxDynamicSharedMemorySize, SMEM2);
        attr_done = true;
    }

    // 1) zero counters + pre-round weights (2.6 MB)
    prep<<<256, 256>>>(W1l, W1r, W2l, W2r);

    // 2) layer-0 mask + bucket-by-dst
    compact_edges<0><<<E0c / 256, 256>>>(src0, dst0, val0, ts, timep, intvp, nullptr);

    // 3) layer-0 gather + mean (warp per dst, 2-edge unrolled)
    gather_mean<0><<<(N1c * 32 + 255) / 256, 256>>>(x);

    // 4) GEMM1 (tf32, 2-stage; agg+B raw, x-half cvt) + bias + BN + leaky -> g_h
    {
        dim3 grid(DHID / 128, (N1c + 127) / 128);
        gemm_tf32<1, 4, 4><<<grid, 256, SMEM1>>>(x, b1, g1, bt1, rm1, rv1, nullptr);
    }

    // 5) layer-1 mask + bucket (+ mask1 output)
    compact_edges<1><<<E1c / 256, 256>>>(src1, dst1, val1, ts, timep, intvp, mask_out);

    // 6) layer-1 gather + mean
    gather_mean<1><<<(N2c * 32 + 255) / 256, 256>>>(nullptr);

    // 7) GEMM2 (tf32, 2-stage, cvt-free) + bias -> out
    {
        dim3 grid(DOUT / 64, (N2c + 63) / 64);
        gemm_tf32<2, 2, 2><<<grid, 256, SMEM2>>>(nullptr, b2,
                                                 nullptr, nullptr, nullptr, nullptr, out);
    }
}

// round 13
// speedup vs baseline: 1.0528x; 1.0275x over previous
#include <cuda_runtime.h>
#include <cuda_bf16.h>
#include <cstdint>

#define N0c   100000
#define N1c   25000
#define N2c   5000
#define E0c   800000
#define E1c   160000
#define DIN   256
#define DHID  256
#define DOUT  128
#define EPSc  1e-5f
#define NEG_SLOPE 0.01f
#define MAXD  48

// ---------------- scratch (device globals) ----------------
__device__ float g_agg1[(size_t)N1c * DIN];   // mean-aggregated
__device__ float g_h[(size_t)N1c * DHID];
__device__ float g_agg2[(size_t)N2c * DHID];
__device__ int   g_icnt1[N1c];
__device__ int   g_icnt2[N2c];
__device__ int   g_slot1[(size_t)N1c * MAXD];
__device__ int   g_slot2[(size_t)N2c * MAXD];

// ---------------- zero counters only ----------------
__global__ void zero_counts() {
    int i = blockIdx.x * blockDim.x + threadIdx.x;
    int stride = gridDim.x * blockDim.x;
    for (int k = i; k < N1c; k += stride) g_icnt1[k] = 0;
    for (int k = i; k < N2c; k += stride) g_icnt2[k] = 0;
}

// ---------------- phase A: mask + bucket edges by dst (thread per edge) ----------------
template <int LAYER>
__global__ void compact_edges(const int* __restrict__ src,
                              const int* __restrict__ dst,
                              const int* __restrict__ val,
                              const int* __restrict__ ts,
                              const int* __restrict__ time_p,
                              const int* __restrict__ interval_p,
                              float* __restrict__ mask_out) {
    int e = blockIdx.x * blockDim.x + threadIdx.x;
    int t0 = __ldg(time_p);
    int iv = __ldg(interval_p);
    int t = __ldg(&ts[__ldg(&val[e])]);
    bool m = (t >= t0) && (t < t0 + iv);

    if (LAYER == 1 && mask_out != nullptr) mask_out[e] = m ? 1.0f : 0.0f;
    if (!m) return;

    int d = __ldg(&dst[e]);
    int* cnt = (LAYER == 0) ? g_icnt1 : g_icnt2;
    int* slot = (LAYER == 0) ? g_slot1 : g_slot2;
    int p = atomicAdd(&cnt[d], 1);
    if (p < MAXD) slot[(size_t)d * MAXD + p] = __ldg(&src[e]);
}

// ---------------- phase B: TWO warps per dst node (half-row each), 4-edge unrolled ----------------
template <int LAYER>
__global__ void gather_mean(const float* __restrict__ feat) {
    constexpr int NR = (LAYER == 0) ? N1c : N2c;
    const int* cnt = (LAYER == 0) ? g_icnt1 : g_icnt2;
    const int* slot = (LAYER == 0) ? g_slot1 : g_slot2;
    const float* fsrc = (LAYER == 0) ? feat : (const float*)g_h;
    float* agg = (LAYER == 0) ? g_agg1 : g_agg2;

    int gw = (blockIdx.x * blockDim.x + threadIdx.x) >> 5;  // global warp id
    int w = gw >> 1;           // dst node
    int half = gw & 1;         // which 128-float half of the row
    if (w >= NR) return;
    int lane = threadIdx.x & 31;
    int off = half * 32 + lane;  // float4 index within the 64-float4 row

    int deg = __ldg(&cnt[w]);
    int dc = (deg < MAXD) ? deg : MAXD;
    const int* sl = slot + (size_t)w * MAXD;

    float4 s = make_float4(0.f, 0.f, 0.f, 0.f);
    int e = 0;
    for (; e + 4 <= dc; e += 4) {
        int i0 = __ldg(&sl[e]);
        int i1 = __ldg(&sl[e + 1]);
        int i2 = __ldg(&sl[e + 2]);
        int i3 = __ldg(&sl[e + 3]);
        float4 a = __ldg(&((const float4*)(fsrc + (size_t)i0 * DHID))[off]);
        float4 b = __ldg(&((const float4*)(fsrc + (size_t)i1 * DHID))[off]);
        float4 c = __ldg(&((const float4*)(fsrc + (size_t)i2 * DHID))[off]);
        float4 d = __ldg(&((const float4*)(fsrc + (size_t)i3 * DHID))[off]);
        s.x += (a.x + b.x) + (c.x + d.x);
        s.y += (a.y + b.y) + (c.y + d.y);
        s.z += (a.z + b.z) + (c.z + d.z);
        s.w += (a.w + b.w) + (c.w + d.w);
    }
    for (; e < dc; e++) {
        int i0 = __ldg(&sl[e]);
        float4 a = __ldg(&((const float4*)(fsrc + (size_t)i0 * DHID))[off]);
        s.x += a.x; s.y += a.y; s.z += a.z; s.w += a.w;
    }
    float r = 1.0f / (float)((deg > 0) ? deg : 1);
    s.x *= r; s.y *= r; s.z *= r; s.w *= r;
    ((float4*)(agg + (size_t)w * DHID))[off] = s;
}

// ---------------- TF32 tensor-core GEMM, cp.async 2-stage (R7-exact) ----------------
__device__ __forceinline__ uint32_t f2tf(float f) {
    uint32_t u;
    asm("cvt.rna.tf32.f32 %0, %1;" : "=r"(u) : "f"(f));
    return u;
}

__device__ __forceinline__ void mma_tf32(float* c, const uint32_t* a, const uint32_t* b) {
    asm volatile(
        "mma.sync.aligned.m16n8k8.row.col.f32.tf32.tf32.f32 "
        "{%0,%1,%2,%3}, {%4,%5,%6,%7}, {%8,%9}, {%0,%1,%2,%3};"
        : "+f"(c[0]), "+f"(c[1]), "+f"(c[2]), "+f"(c[3])
        : "r"(a[0]), "r"(a[1]), "r"(a[2]), "r"(a[3]), "r"(b[0]), "r"(b[1]));
}

__device__ __forceinline__ void cp_async16(uint32_t dst, const void* src, int srcsize) {
    asm volatile("cp.async.cg.shared.global [%0], [%1], 16, %2;"
                 :: "r"(dst), "l"(src), "r"(srcsize));
}

// Block tile: BM = IM*32, BN = JN*32, BK = 32; 8 warps (2m x 4n); 2-stage.
template <int LAYER, int IM, int JN>
__global__ __launch_bounds__(256, 2) void gemm_tf32(
    const float* __restrict__ xroot,
    const float* __restrict__ B1, const float* __restrict__ B2,
    const float* __restrict__ bias,
    const float* __restrict__ gam, const float* __restrict__ bet,
    const float* __restrict__ rm, const float* __restrict__ rv,
    float* __restrict__ outp) {
    constexpr int M = (LAYER == 1) ? N1c : N2c;
    constexpr int N = (LAYER == 1) ? DHID : DOUT;
    constexpr bool DO_BN = (LAYER == 1);
    constexpr int BM = IM * 32;
    constexpr int BN = JN * 32;
    constexpr int AS_STRIDE = 36;
    constexpr int BS_STRIDE = BN + 4;
    constexpr int ASZ = BM * AS_STRIDE;
    constexpr int BSZ = 32 * BS_STRIDE;
    constexpr int BUFSZ = ASZ + BSZ;
    constexpr int B4 = BN / 4;

    const float* Aagg  = (LAYER == 1) ? g_agg1 : g_agg2;
    const float* Aroot = (LAYER == 1) ? xroot : (const float*)g_h;
    float* Out = (LAYER == 1) ? g_h : outp;

    extern __shared__ __align__(16) float sm[];

    const int tid = threadIdx.x;
    const int lane = tid & 31;
    const int wid = tid >> 5;
    const int wm = wid >> 2;
    const int wn = wid & 3;
    const int bm = blockIdx.y * BM;
    const int bn = blockIdx.x * BN;

    const uint32_t smbase = (uint32_t)__cvta_generic_to_shared(sm);

    auto load_tile = [&](int t, int buf) {
        const bool ia = (t < 8);
        const float* Aptr = ia ? Aagg : Aroot;
        const float* Bptr = ia ? B1 : B2;
        const int kk = (t * 32) & 255;
        const uint32_t abase = smbase + (uint32_t)(buf * BUFSZ) * 4u;
        const uint32_t bbase = abase + (uint32_t)ASZ * 4u;
#pragma unroll
        for (int i = 0; i < IM; i++) {
            int idx = tid + i * 256;
            int m = idx >> 3, kg = idx & 7;
            int row = bm + m;
            int ok = (row < M) ? 16 : 0;
            int rc = (row < M) ? row : (M - 1);
            cp_async16(abase + (uint32_t)(m * AS_STRIDE + 4 * kg) * 4u,
                       Aptr + (size_t)rc * 256 + kk + 4 * kg, ok);
        }
#pragma unroll
        for (int i = 0; i < JN; i++) {
            int idx = tid + i * 256;
            int k = idx / B4, ng = idx % B4;
            cp_async16(bbase + (uint32_t)(k * BS_STRIDE + 4 * ng) * 4u,
                       Bptr + (size_t)(kk + k) * N + bn + 4 * ng, 16);
        }
        asm volatile("cp.async.commit_group;");
    };

    float acc[IM][JN][4];
#pragma unroll
    for (int i = 0; i < IM; i++)
#pragma unroll
        for (int j = 0; j < JN; j++)
#pragma unroll
            for (int r = 0; r < 4; r++) acc[i][j][r] = 0.0f;

    load_tile(0, 0);

    for (int t = 0; t < 16; t++) {
        if (t + 1 < 16) {
            load_tile(t + 1, (t + 1) & 1);
            asm volatile("cp.async.wait_group 1;");
        } else {
            asm volatile("cp.async.wait_group 0;");
        }
        __syncthreads();

        const float* As = sm + (t & 1) * BUFSZ;
        const float* Bs = As + ASZ;

#pragma unroll
        for (int ks = 0; ks < 4; ks++) {
            uint32_t af[IM][4], bf[JN][2];
            const int col = ks * 8 + (lane & 3);
            const int rbase = wm * (IM * 16) + (lane >> 2);
#pragma unroll
            for (int i = 0; i < IM; i++) {
                int r = rbase + i * 16;
                af[i][0] = f2tf(As[r * AS_STRIDE + col]);
                af[i][1] = f2tf(As[(r + 8) * AS_STRIDE + col]);
                af[i][2] = f2tf(As[r * AS_STRIDE + col + 4]);
                af[i][3] = f2tf(As[(r + 8) * AS_STRIDE + col + 4]);
            }
#pragma unroll
            for (int j = 0; j < JN; j++) {
                int n = wn * (JN * 8) + j * 8 + (lane >> 2);
                bf[j][0] = f2tf(Bs[col * BS_STRIDE + n]);
                bf[j][1] = f2tf(Bs[(col + 4) * BS_STRIDE + n]);
            }
#pragma unroll
            for (int i = 0; i < IM; i++)
#pragma unroll
                for (int j = 0; j < JN; j++) mma_tf32(acc[i][j], af[i], bf[j]);
        }
        __syncthreads();
    }

    float cb[JN][2], cs[JN][2], csh[JN][2];
#pragma unroll
    for (int j = 0; j < JN; j++) {
#pragma unroll
        for (int q = 0; q < 2; q++) {
            int c = bn + wn * (JN * 8) + j * 8 + 2 * (lane & 3) + q;
            cb[j][q] = bias[c];
            if (DO_BN) {
                float s = gam[c] * rsqrtf(rv[c] + EPSc);
                cs[j][q] = s;
                csh[j][q] = bet[c] - rm[c] * s;
            }
        }
    }

#pragma unroll
    for (int i = 0; i < IM; i++) {
        int r0 = bm + wm * (IM * 16) + i * 16 + (lane >> 2);
#pragma unroll
        for (int j = 0; j < JN; j++) {
            int c = bn + wn * (JN * 8) + j * 8 + 2 * (lane & 3);
#pragma unroll
            for (int half = 0; half < 2; half++) {
                int r = r0 + half * 8;
                if (r >= M) continue;
                float y0 = acc[i][j][2 * half + 0] + cb[j][0];
                float y1 = acc[i][j][2 * half + 1] + cb[j][1];
                if (DO_BN) {
                    y0 = y0 * cs[j][0] + csh[j][0];
                    y1 = y1 * cs[j][1] + csh[j][1];
                    y0 = (y0 >= 0.f) ? y0 : NEG_SLOPE * y0;
                    y1 = (y1 >= 0.f) ? y1 : NEG_SLOPE * y1;
                }
                float2 o = make_float2(y0, y1);
                *(float2*)(Out + (size_t)r * N + c) = o;
            }
        }
    }
}

#define SMEM1 ((128 * 36 + 32 * 132) * 2 * 4)
#define SMEM2 ((64 * 36 + 32 * 68) * 2 * 4)

// ---------------- launch ----------------
extern "C" void kernel_launch(void* const* d_in, const int* in_sizes, int n_in,
                              void* d_out, int out_size) {
    const float* x    = (const float*)d_in[0];
    const int* src0   = (const int*)d_in[1];
    const int* dst0   = (const int*)d_in[2];
    const int* val0   = (const int*)d_in[3];
    const int* src1   = (const int*)d_in[4];
    const int* dst1   = (const int*)d_in[5];
    const int* val1   = (const int*)d_in[6];
    const int* ts     = (const int*)d_in[7];
    const int* timep  = (const int*)d_in[8];
    const int* intvp  = (const int*)d_in[9];
    const float* W1l  = (const float*)d_in[10];
    const float* W1r  = (const float*)d_in[11];
    const float* b1   = (const float*)d_in[12];
    const float* g1   = (const float*)d_in[13];
    const float* bt1  = (const float*)d_in[14];
    const float* rm1  = (const float*)d_in[15];
    const float* rv1  = (const float*)d_in[16];
    const float* W2l  = (const float*)d_in[17];
    const float* W2r  = (const float*)d_in[18];
    const float* b2   = (const float*)d_in[19];

    float* out = (float*)d_out;
    float* mask_out = (out_size >= N2c * DOUT + E1c) ? (out + N2c * DOUT) : nullptr;

    static bool attr_done = false;
    if (!attr_done) {
        cudaFuncSetAttribute((const void*)gemm_tf32<1, 4, 4>,
                             cudaFuncAttributeMaxDynamicSharedMemorySize, SMEM1);
        cudaFuncSetAttribute((const void*)gemm_tf32<2, 2, 2>,
                             cudaFuncAttributeMaxDynamicSharedMemorySize, SMEM2);
        attr_done = true;
    }

    // 1) zero per-dst counters
    zero_counts<<<128, 256>>>();

    // 2) layer-0 mask + bucket-by-dst
    compact_edges<0><<<E0c / 256, 256>>>(src0, dst0, val0, ts, timep, intvp, nullptr);

    // 3) layer-0 gather + mean (2 warps per dst, 4-edge unrolled)
    gather_mean<0><<<(N1c * 64 + 255) / 256, 256>>>(x);

    // 4) GEMM1 (tf32, 2-stage, R7-exact) + bias + BN + leaky -> g_h
    {
        dim3 grid(DHID / 128, (N1c + 127) / 128);
        gemm_tf32<1, 4, 4><<<grid, 256, SMEM1>>>(x, W1l, W1r, b1, g1, bt1, rm1, rv1, nullptr);
    }

    // 5) layer-1 mask + bucket (+ mask1 output)
    compact_edges<1><<<E1c / 256, 256>>>(src1, dst1, val1, ts, timep, intvp, mask_out);

    // 6) layer-1 gather + mean
    gather_mean<1><<<(N2c * 64 + 255) / 256, 256>>>(nullptr);

    // 7) GEMM2 (tf32, 2-stage) + bias -> out
    {
        dim3 grid(DOUT / 64, (N2c + 63) / 64);
        gemm_tf32<2, 2, 2><<<grid, 256, SMEM2>>>(nullptr, W2l, W2r, b2,
                                                 nullptr, nullptr, nullptr, nullptr, out);
    }
}